// round 8
// baseline (speedup 1.0000x reference)
#include <cuda_runtime.h>
#include <cuda_bf16.h>
#include <math.h>

// Problem dims
#define T_DIM 128
#define B_DIM 256
#define OBS_DIM 1024
#define PS 512
#define HID 512
#define GDIM 2048
#define ACT 21
#define M_ROWS (T_DIM * B_DIM)   // 32768
#define NCTA 128                 // persistent scan grid size (must be <= #SMs)

// ---------------- scratch ------------------------------------------------------
__device__ float g_priv1[M_ROWS * HID];   // priv_o (final, persists through head)
__device__ float g_tmp[M_ROWS * HID];     // priv intermediate
__device__ float g_publx[M_ROWS * HID];   // publ_x / priv intermediate 2
__device__ float g_xg[M_ROWS * GDIM];     // x_gates
__device__ float g_h[M_ROWS * HID];       // h at every t
__device__ float g_c[B_DIM * HID];        // c state (final)
__device__ int   g_bar[T_DIM];            // scan barrier counters

#define DONE(p, idx) (((const unsigned int*)(p))[idx] != 0u)

// ---------------- tf32 mma helpers --------------------------------------------
__device__ __forceinline__ unsigned f2tf32(float x) {
    unsigned u;
    asm("cvt.rna.tf32.f32 %0, %1;" : "=r"(u) : "f"(x));
    return u;
}

__device__ __forceinline__ void mma_tf32(float* d, const unsigned* a, const unsigned* b) {
    asm volatile(
        "mma.sync.aligned.m16n8k8.row.col.f32.tf32.tf32.f32 "
        "{%0,%1,%2,%3}, {%4,%5,%6,%7}, {%8,%9}, {%0,%1,%2,%3};"
        : "+f"(d[0]), "+f"(d[1]), "+f"(d[2]), "+f"(d[3])
        : "r"(a[0]), "r"(a[1]), "r"(a[2]), "r"(a[3]),
          "r"(b[0]), "r"(b[1]));
}

// ---------------- tf32 GEMM: C = act(A @ W + bias) -----------------------------
// BM=128, BN=128, BK=32. 256 threads = 8 warps (2 m x 4 n), warp tile 64x32.
// Double-buffered smem with register-staged prefetch (distance 1).
#define BM 128
#define BN 128
#define BK 32

__global__ __launch_bounds__(256) void gemm_tf32(
    const float* __restrict__ A, int lda,
    const float* __restrict__ W,      // K x N row-major
    int N, int K,
    const float* __restrict__ bias,
    float* __restrict__ C,
    int relu)
{
    __shared__ unsigned As[2][BM][36];   // [buf][m][k]
    __shared__ unsigned Bs[2][BN][36];   // [buf][n][k]

    const int tid  = threadIdx.x;
    const int warp = tid >> 5;
    const int lane = tid & 31;
    const int wm = warp >> 2;
    const int wn = warp & 3;
    const int row0 = blockIdx.y * BM;
    const int col0 = blockIdx.x * BN;
    const int q = lane >> 2;
    const int r = lane & 3;

    // A staging coords: 4 chunks, lin = i*256+tid -> m = lin>>3, k4 = (lin&7)*4
    const int am = tid >> 3;              // base row for chunk i: am + i*32
    const int ak4 = (tid & 7) * 4;
    // B staging coords: 16 scalars, idx = i*8+warp -> k=(idx&7)*4+r, n=(idx>>3)*8+q

    float acc[4][4][4];
#pragma unroll
    for (int mt = 0; mt < 4; mt++)
#pragma unroll
        for (int nt = 0; nt < 4; nt++)
#pragma unroll
            for (int e = 0; e < 4; e++) acc[mt][nt][e] = 0.f;

    const int niter = K / BK;
    float4 av[4];
    float  bv[16];

    // prologue: load + store tile 0
#pragma unroll
    for (int i = 0; i < 4; i++)
        av[i] = *(const float4*)(A + (size_t)(row0 + am + i * 32) * lda + ak4);
#pragma unroll
    for (int i = 0; i < 16; i++) {
        int idx = i * 8 + warp;
        int k = (idx & 7) * 4 + r;
        int n = (idx >> 3) * 8 + q;
        bv[i] = W[(size_t)k * N + col0 + n];
    }
#pragma unroll
    for (int i = 0; i < 4; i++) {
        int m = am + i * 32;
        As[0][m][ak4 + 0] = f2tf32(av[i].x);
        As[0][m][ak4 + 1] = f2tf32(av[i].y);
        As[0][m][ak4 + 2] = f2tf32(av[i].z);
        As[0][m][ak4 + 3] = f2tf32(av[i].w);
    }
#pragma unroll
    for (int i = 0; i < 16; i++) {
        int idx = i * 8 + warp;
        int k = (idx & 7) * 4 + r;
        int n = (idx >> 3) * 8 + q;
        Bs[0][n][k] = f2tf32(bv[i]);
    }

    for (int kt = 0; kt < niter; kt++) {
        __syncthreads();
        const int cur = kt & 1;
        if (kt + 1 < niter) {
            int k0 = (kt + 1) * BK;
#pragma unroll
            for (int i = 0; i < 4; i++)
                av[i] = *(const float4*)(A + (size_t)(row0 + am + i * 32) * lda + k0 + ak4);
#pragma unroll
            for (int i = 0; i < 16; i++) {
                int idx = i * 8 + warp;
                int k = (idx & 7) * 4 + r;
                int n = (idx >> 3) * 8 + q;
                bv[i] = W[(size_t)(k0 + k) * N + col0 + n];
            }
        }

#pragma unroll
        for (int ks = 0; ks < 4; ks++) {
            unsigned af[4][4], bf[4][2];
            int c = ks * 8 + r;
#pragma unroll
            for (int mt = 0; mt < 4; mt++) {
                int rr = wm * 64 + mt * 16 + q;
                af[mt][0] = As[cur][rr][c];
                af[mt][1] = As[cur][rr + 8][c];
                af[mt][2] = As[cur][rr][c + 4];
                af[mt][3] = As[cur][rr + 8][c + 4];
            }
#pragma unroll
            for (int nt = 0; nt < 4; nt++) {
                int nn = wn * 32 + nt * 8 + q;
                bf[nt][0] = Bs[cur][nn][c];
                bf[nt][1] = Bs[cur][nn][c + 4];
            }
#pragma unroll
            for (int mt = 0; mt < 4; mt++)
#pragma unroll
                for (int nt = 0; nt < 4; nt++)
                    mma_tf32(acc[mt][nt], af[mt], bf[nt]);
        }

        if (kt + 1 < niter) {
            const int nxt = cur ^ 1;
#pragma unroll
            for (int i = 0; i < 4; i++) {
                int m = am + i * 32;
                As[nxt][m][ak4 + 0] = f2tf32(av[i].x);
                As[nxt][m][ak4 + 1] = f2tf32(av[i].y);
                As[nxt][m][ak4 + 2] = f2tf32(av[i].z);
                As[nxt][m][ak4 + 3] = f2tf32(av[i].w);
            }
#pragma unroll
            for (int i = 0; i < 16; i++) {
                int idx = i * 8 + warp;
                int k = (idx & 7) * 4 + r;
                int n = (idx >> 3) * 8 + q;
                Bs[nxt][n][k] = f2tf32(bv[i]);
            }
        }
    }

#pragma unroll
    for (int mt = 0; mt < 4; mt++) {
        int rbase = row0 + wm * 64 + mt * 16 + q;
#pragma unroll
        for (int nt = 0; nt < 4; nt++) {
            int cbase = col0 + wn * 32 + nt * 8 + 2 * r;
            float v0 = acc[mt][nt][0];
            float v1 = acc[mt][nt][1];
            float v2 = acc[mt][nt][2];
            float v3 = acc[mt][nt][3];
            if (bias) {
                float b0 = bias[cbase], b1 = bias[cbase + 1];
                v0 += b0; v1 += b1; v2 += b0; v3 += b1;
            }
            if (relu) {
                v0 = fmaxf(v0, 0.f); v1 = fmaxf(v1, 0.f);
                v2 = fmaxf(v2, 0.f); v3 = fmaxf(v3, 0.f);
            }
            C[(size_t)rbase * N + cbase]           = v0;
            C[(size_t)rbase * N + cbase + 1]       = v1;
            C[(size_t)(rbase + 8) * N + cbase]     = v2;
            C[(size_t)(rbase + 8) * N + cbase + 1] = v3;
        }
    }
}

// ---------------- persistent LSTM scan -----------------------------------------
// 128 CTAs (32 hid-blocks x 4 batch-blocks), all co-resident (1 CTA/SM).
// Wh slice [512][64] resident in smem (tf32) for all 128 steps; c in registers.
#define SCAN_SMEM (147456 + 18432)

__global__ void bar_reset_kernel() {
    if (threadIdx.x < T_DIM) g_bar[threadIdx.x] = 0;
}

__global__ __launch_bounds__(256, 1) void lstm_scan(
    const float* __restrict__ Wh,      // [512][2048]
    const float* __restrict__ xg,      // [T][B][2048]
    const float* __restrict__ blstm,   // [2048]
    const void* __restrict__ dones,    // [T][B] bool words
    const float* __restrict__ h0,      // [B][512]
    const float* __restrict__ c0,      // [B][512]
    float* __restrict__ hbuf,          // [T][B][512]
    float* __restrict__ cst)           // [B][512]
{
    extern __shared__ char dsm[];
    unsigned (*WhS)[64][36] = (unsigned(*)[64][36])dsm;             // [16][64][36]
    unsigned (*As)[64][36]  = (unsigned(*)[64][36])(dsm + 147456);  // [2][64][36]
    float (*gsm)[68]        = (float(*)[68])(dsm + 147456);         // aliases As

    const int tid  = threadIdx.x;
    const int warp = tid >> 5;
    const int lane = tid & 31;
    const int wm = warp >> 2;        // 0..1
    const int wn = warp & 3;         // 0..3 == gate index
    const int q = lane >> 2;         // 0..7
    const int r = lane & 3;          // 0..3
    const int hid0 = blockIdx.x * 16;
    const int b0   = blockIdx.y * 64;

    // ---- load Wh slice into smem (tf32), gate-interleaved cols ----
#pragma unroll 4
    for (int kk = 0; kk < 16; kk++) {
#pragma unroll
        for (int i = 0; i < 8; i++) {
            int idx = i * 8 + warp;
            int k = (idx & 7) * 4 + r;
            int n = (idx >> 3) * 8 + q;
            int wcol = (n >> 4) * HID + hid0 + (n & 15);
            WhS[kk][n][k] = f2tf32(Wh[(size_t)(kk * 32 + k) * GDIM + wcol]);
        }
    }

    // ---- c state in registers ----
    float c_reg[4];
#pragma unroll
    for (int it = 0; it < 4; it++) {
        int idx = it * 256 + tid;
        int bl = idx >> 4, j = idx & 15;
        c_reg[it] = c0[(size_t)(b0 + bl) * HID + hid0 + j];
    }

    // ---- hoist b_lstm (constant across steps) ----
    float2 bbr[2][2];
#pragma unroll
    for (int mtb = 0; mtb < 1; mtb++) { }
#pragma unroll
    for (int nt = 0; nt < 2; nt++) {
        int wcol = wn * HID + hid0 + nt * 8 + 2 * r;
        bbr[0][nt] = *(const float2*)(blstm + wcol);
    }

    __syncthreads();

    const int lm0 = tid >> 3;              // A-stage row (0..31)
    const int lk4 = (tid & 7) * 4;         // A-stage k offset

    for (int t = 0; t < T_DIM; t++) {
        const float* hp = t ? (hbuf + (size_t)(t - 1) * B_DIM * HID) : h0;
        const unsigned* dn = (const unsigned*)dones + (size_t)t * B_DIM;
        const float* xgt = xg + (size_t)t * B_DIM * GDIM;

        // prefetch this step's dones words (A-mask + pointwise masks)
        const unsigned dm0 = dn[b0 + lm0];
        const unsigned dm1 = dn[b0 + 32 + lm0];
        unsigned dnp[4];
#pragma unroll
        for (int it = 0; it < 4; it++) {
            int idx = it * 256 + tid;
            dnp[it] = dn[b0 + (idx >> 4)];
        }
        // prefetch this step's xg values (consumed in gate staging)
        float2 xr[2][2][2];
#pragma unroll
        for (int mt = 0; mt < 2; mt++) {
            int rl = wm * 32 + mt * 16 + q;
#pragma unroll
            for (int nt = 0; nt < 2; nt++) {
                int wcol = wn * HID + hid0 + nt * 8 + 2 * r;
                xr[mt][nt][0] = *(const float2*)(xgt + (size_t)(b0 + rl) * GDIM + wcol);
                xr[mt][nt][1] = *(const float2*)(xgt + (size_t)(b0 + rl + 8) * GDIM + wcol);
            }
        }

        float acc[2][2][4];
#pragma unroll
        for (int mt = 0; mt < 2; mt++)
#pragma unroll
            for (int nt = 0; nt < 2; nt++)
#pragma unroll
                for (int e = 0; e < 4; e++) acc[mt][nt][e] = 0.f;

        // prefetch A tile 0
        float4 av0, av1;
        av0 = *(const float4*)(hp + (size_t)(b0 + lm0) * HID + lk4);
        av1 = *(const float4*)(hp + (size_t)(b0 + 32 + lm0) * HID + lk4);
        if (dm0) av0 = make_float4(0.f, 0.f, 0.f, 0.f);
        if (dm1) av1 = make_float4(0.f, 0.f, 0.f, 0.f);
        As[0][lm0][lk4 + 0] = f2tf32(av0.x);
        As[0][lm0][lk4 + 1] = f2tf32(av0.y);
        As[0][lm0][lk4 + 2] = f2tf32(av0.z);
        As[0][lm0][lk4 + 3] = f2tf32(av0.w);
        As[0][32 + lm0][lk4 + 0] = f2tf32(av1.x);
        As[0][32 + lm0][lk4 + 1] = f2tf32(av1.y);
        As[0][32 + lm0][lk4 + 2] = f2tf32(av1.z);
        As[0][32 + lm0][lk4 + 3] = f2tf32(av1.w);

#pragma unroll
        for (int kk = 0; kk < 16; kk++) {
            __syncthreads();
            if (kk < 15) {
                int k0 = (kk + 1) * 32;
                av0 = *(const float4*)(hp + (size_t)(b0 + lm0) * HID + k0 + lk4);
                av1 = *(const float4*)(hp + (size_t)(b0 + 32 + lm0) * HID + k0 + lk4);
            }
            const int cur = kk & 1;
#pragma unroll
            for (int ks = 0; ks < 4; ks++) {
                unsigned af[2][4], bf[2][2];
                int c = ks * 8 + r;
#pragma unroll
                for (int mt = 0; mt < 2; mt++) {
                    int rr = wm * 32 + mt * 16 + q;
                    af[mt][0] = As[cur][rr][c];
                    af[mt][1] = As[cur][rr + 8][c];
                    af[mt][2] = As[cur][rr][c + 4];
                    af[mt][3] = As[cur][rr + 8][c + 4];
                }
#pragma unroll
                for (int nt = 0; nt < 2; nt++) {
                    int nn = wn * 16 + nt * 8 + q;
                    bf[nt][0] = WhS[kk][nn][c];
                    bf[nt][1] = WhS[kk][nn][c + 4];
                }
#pragma unroll
                for (int mt = 0; mt < 2; mt++)
#pragma unroll
                    for (int nt = 0; nt < 2; nt++)
                        mma_tf32(acc[mt][nt], af[mt], bf[nt]);
            }
            if (kk < 15) {
                const int nxt = cur ^ 1;
                if (dm0) av0 = make_float4(0.f, 0.f, 0.f, 0.f);
                if (dm1) av1 = make_float4(0.f, 0.f, 0.f, 0.f);
                As[nxt][lm0][lk4 + 0] = f2tf32(av0.x);
                As[nxt][lm0][lk4 + 1] = f2tf32(av0.y);
                As[nxt][lm0][lk4 + 2] = f2tf32(av0.z);
                As[nxt][lm0][lk4 + 3] = f2tf32(av0.w);
                As[nxt][32 + lm0][lk4 + 0] = f2tf32(av1.x);
                As[nxt][32 + lm0][lk4 + 1] = f2tf32(av1.y);
                As[nxt][32 + lm0][lk4 + 2] = f2tf32(av1.z);
                As[nxt][32 + lm0][lk4 + 3] = f2tf32(av1.w);
            }
        }
        __syncthreads();   // compute done before gsm (aliases As) is written

        // ---- stage gates into smem (+xg +b_lstm, prefetched) ----
#pragma unroll
        for (int mt = 0; mt < 2; mt++) {
            int rl = wm * 32 + mt * 16 + q;
#pragma unroll
            for (int nt = 0; nt < 2; nt++) {
                int cl = wn * 16 + nt * 8 + 2 * r;
                float2 bb = bbr[0][nt];
                float2 x0 = xr[mt][nt][0];
                float2 x1 = xr[mt][nt][1];
                gsm[rl][cl]         = acc[mt][nt][0] + x0.x + bb.x;
                gsm[rl][cl + 1]     = acc[mt][nt][1] + x0.y + bb.y;
                gsm[rl + 8][cl]     = acc[mt][nt][2] + x1.x + bb.x;
                gsm[rl + 8][cl + 1] = acc[mt][nt][3] + x1.y + bb.y;
            }
        }
        __syncthreads();

        // ---- pointwise LSTM update (c in registers) ----
        float* hout = hbuf + (size_t)t * B_DIM * HID;
#pragma unroll
        for (int it = 0; it < 4; it++) {
            int idx = it * 256 + tid;
            int bl = idx >> 4, j = idx & 15;
            int b = b0 + bl, hid = hid0 + j;
            float iv = gsm[bl][j];
            float fv = gsm[bl][16 + j];
            float gv = gsm[bl][32 + j];
            float ov = gsm[bl][48 + j];
            float is = 1.f / (1.f + expf(-iv));
            float fs = 1.f / (1.f + expf(-fv));
            float os = 1.f / (1.f + expf(-ov));
            float gt = tanhf(gv);
            float cm = dnp[it] ? 0.f : c_reg[it];
            float nc = fs * cm + is * gt;
            c_reg[it] = nc;
            hout[(size_t)b * HID + hid] = os * tanhf(nc);
            if (t == T_DIM - 1)
                cst[(size_t)b * HID + hid] = nc;
        }

        // ---- grid barrier between steps ----
        if (t < T_DIM - 1) {
            __threadfence();
            __syncthreads();
            if (tid == 0) {
                atomicAdd(&g_bar[t], 1);
                while (*(volatile int*)&g_bar[t] < NCTA) { }
            }
            __syncthreads();
        }
    }
}

// ---------------- head ---------------------------------------------------------
__global__ __launch_bounds__(256) void head_kernel(
    const float* __restrict__ privo, const float* __restrict__ hbuf,
    const float* __restrict__ Wv, const float* __restrict__ bv,
    const float* __restrict__ Wa, const float* __restrict__ ba,
    float* __restrict__ outq)
{
    __shared__ float so[8][HID];
    const int tid = threadIdx.x;
    const int w = tid >> 5, lane = tid & 31;
    const int row = blockIdx.x * 8 + w;

    for (int k = lane; k < HID; k += 32)
        so[w][k] = privo[(size_t)row * HID + k] * hbuf[(size_t)row * HID + k];
    __syncwarp();

    float acc = 0.f;
    if (lane < 21) {
        for (int k = 0; k < HID; k++)
            acc += so[w][k] * Wa[k * ACT + lane];
    } else if (lane == 21) {
        for (int k = 0; k < HID; k++)
            acc += so[w][k] * Wv[k];
    }
    float v = __shfl_sync(0xffffffffu, acc, 21);
    if (lane < ACT)
        outq[(size_t)row * ACT + lane] = acc + ba[lane] + v + bv[0];
}

__global__ void tail_copy_kernel(const float* __restrict__ c,
                                 const float* __restrict__ hT,
                                 float* __restrict__ out)
{
    int i = blockIdx.x * blockDim.x + threadIdx.x;
    if (i < B_DIM * HID) {
        out[i] = c[i];
        out[B_DIM * HID + i] = hT[i];
    }
}

// -----------------------------------------------------------------------------
extern "C" void kernel_launch(void* const* d_in, const int* in_sizes, int n_in,
                              void* d_out, int out_size)
{
    const float* c0    = (const float*)d_in[0];
    const float* h0    = (const float*)d_in[1];
    const float* obs   = (const float*)d_in[2];
    const void*  dones = d_in[3];
    const float* Wp1   = (const float*)d_in[4];
    const float* bp1   = (const float*)d_in[5];
    const float* Wp2   = (const float*)d_in[6];
    const float* bp2   = (const float*)d_in[7];
    const float* Wp3   = (const float*)d_in[8];
    const float* bp3   = (const float*)d_in[9];
    const float* Wpub  = (const float*)d_in[10];
    const float* bpub  = (const float*)d_in[11];
    const float* Wi    = (const float*)d_in[12];
    const float* Wh    = (const float*)d_in[13];
    const float* blstm = (const float*)d_in[14];
    const float* Wv    = (const float*)d_in[15];
    const float* bv    = (const float*)d_in[16];
    const float* Wa    = (const float*)d_in[17];
    const float* ba    = (const float*)d_in[18];
    float* out = (float*)d_out;

    float *priv1, *tmp, *publx, *xg, *hbuf, *cst;
    cudaGetSymbolAddress((void**)&priv1, g_priv1);
    cudaGetSymbolAddress((void**)&tmp,   g_tmp);
    cudaGetSymbolAddress((void**)&publx, g_publx);
    cudaGetSymbolAddress((void**)&xg,    g_xg);
    cudaGetSymbolAddress((void**)&hbuf,  g_h);
    cudaGetSymbolAddress((void**)&cst,   g_c);

    static int smem_set = 0;
    if (!smem_set) {
        cudaFuncSetAttribute(lstm_scan,
                             cudaFuncAttributeMaxDynamicSharedMemorySize,
                             SCAN_SMEM);
        smem_set = 1;
    }

    dim3 blk(256);
    dim3 grid512(HID / BN, M_ROWS / BM);     // (4, 256)
    dim3 grid2048(GDIM / BN, M_ROWS / BM);   // (16, 256)

    // public path
    gemm_tf32<<<grid512, blk>>>(obs + PS, OBS_DIM, Wpub, HID, OBS_DIM - PS, bpub, publx, 1);
    gemm_tf32<<<grid2048, blk>>>(publx,   HID,     Wi,   GDIM, HID,        nullptr, xg, 0);
    // private path (final priv_o in priv1)
    gemm_tf32<<<grid512, blk>>>(obs,   OBS_DIM, Wp1, HID, PS,  bp1, tmp,   1);
    gemm_tf32<<<grid512, blk>>>(tmp,   HID,     Wp2, HID, HID, bp2, publx, 1);
    gemm_tf32<<<grid512, blk>>>(publx, HID,     Wp3, HID, HID, bp3, priv1, 1);

    // LSTM scan: single persistent kernel, barrier counters reset each replay
    bar_reset_kernel<<<1, 128>>>();
    lstm_scan<<<dim3(32, 4), blk, SCAN_SMEM>>>(Wh, xg, blstm, dones, h0, c0,
                                               hbuf, cst);

    // output layout
    const int STATE = B_DIM * HID;
    const int QSZ   = M_ROWS * ACT;
    float* qdst = out;
    int write_states = 0;
    if (out_size >= 2 * STATE + QSZ) { qdst = out + 2 * STATE; write_states = 1; }

    head_kernel<<<M_ROWS / 8, 256>>>(priv1, hbuf, Wv, bv, Wa, ba, qdst);

    if (write_states) {
        tail_copy_kernel<<<(STATE + 255) / 256, 256>>>(
            cst, hbuf + (size_t)(T_DIM - 1) * B_DIM * HID, out);
    }
}

// round 9
// speedup vs baseline: 1.1389x; 1.1389x over previous
#include <cuda_runtime.h>
#include <cuda_bf16.h>
#include <math.h>

// Problem dims
#define T_DIM 128
#define B_DIM 256
#define OBS_DIM 1024
#define PS 512
#define HID 512
#define GDIM 2048
#define ACT 21
#define M_ROWS (T_DIM * B_DIM)   // 32768
#define NCTA 128                 // persistent scan grid size (must be <= #SMs)

// ---------------- scratch ------------------------------------------------------
__device__ float g_priv1[M_ROWS * HID];   // priv_o (final, persists through head)
__device__ float g_tmp[M_ROWS * HID];     // priv intermediate
__device__ float g_publx[M_ROWS * HID];   // publ_x / priv intermediate 2
__device__ float g_xg[M_ROWS * GDIM];     // x_gates
__device__ float g_h[M_ROWS * HID];       // h at every t
__device__ float g_c[B_DIM * HID];        // c state (final)
__device__ int   g_bar[T_DIM];            // scan barrier counters

#define DONE(p, idx) (((const unsigned int*)(p))[idx] != 0u)

// ---------------- tf32 mma helpers --------------------------------------------
__device__ __forceinline__ unsigned f2tf32(float x) {
    unsigned u;
    asm("cvt.rna.tf32.f32 %0, %1;" : "=r"(u) : "f"(x));
    return u;
}

__device__ __forceinline__ void mma_tf32(float* d, const unsigned* a, const unsigned* b) {
    asm volatile(
        "mma.sync.aligned.m16n8k8.row.col.f32.tf32.tf32.f32 "
        "{%0,%1,%2,%3}, {%4,%5,%6,%7}, {%8,%9}, {%0,%1,%2,%3};"
        : "+f"(d[0]), "+f"(d[1]), "+f"(d[2]), "+f"(d[3])
        : "r"(a[0]), "r"(a[1]), "r"(a[2]), "r"(a[3]),
          "r"(b[0]), "r"(b[1]));
}

// ---------------- cp.async helpers ---------------------------------------------
__device__ __forceinline__ void cp16(void* smem_dst, const void* gmem_src) {
    unsigned dst = (unsigned)__cvta_generic_to_shared(smem_dst);
    asm volatile("cp.async.cg.shared.global [%0], [%1], 16;\n"
                 :: "r"(dst), "l"(gmem_src));
}
#define CP_COMMIT() asm volatile("cp.async.commit_group;\n" ::: "memory")
#define CP_WAIT(n)  asm volatile("cp.async.wait_group %0;\n" :: "n"(n) : "memory")

// ---------------- tf32 GEMM: C = act(A @ W + bias) -----------------------------
// BM=128, BN=128, BK=32. 256 threads = 8 warps (2 m x 4 n), warp tile 64x32.
// cp.async double-buffered staging of raw f32; cvt->tf32 at fragment load.
#define BM 128
#define BN 128
#define BK 32

__global__ __launch_bounds__(256, 2) void gemm_tf32(
    const float* __restrict__ A, int lda,
    const float* __restrict__ W,      // K x N row-major
    int N, int K,
    const float* __restrict__ bias,
    float* __restrict__ C,
    int relu)
{
    __shared__ float As[2][BM][36];    // [buf][m][k]  row stride 144B (16B-mult)
    __shared__ float Bs[2][BK][136];   // [buf][k][n]  row stride 544B (16B-mult)

    const int tid  = threadIdx.x;
    const int warp = tid >> 5;
    const int lane = tid & 31;
    const int wm = warp >> 2;
    const int wn = warp & 3;
    const int row0 = blockIdx.y * BM;
    const int col0 = blockIdx.x * BN;
    const int q = lane >> 2;
    const int r = lane & 3;

    const int am  = tid >> 3;          // A stage: rows am + i*32
    const int ak4 = (tid & 7) * 4;     // A stage: k offset (16B chunk)

    float acc[4][4][4];
#pragma unroll
    for (int mt = 0; mt < 4; mt++)
#pragma unroll
        for (int nt = 0; nt < 4; nt++)
#pragma unroll
            for (int e = 0; e < 4; e++) acc[mt][nt][e] = 0.f;

    const int niter = K / BK;

    // ---- async issue of one k-tile into buffer buf ----
    auto issue = [&](int kt, int buf) {
        int k0 = kt * BK;
#pragma unroll
        for (int i = 0; i < 4; i++) {
            int m = am + i * 32;
            cp16(&As[buf][m][ak4], A + (size_t)(row0 + m) * lda + k0 + ak4);
        }
#pragma unroll
        for (int i = 0; i < 4; i++) {
            int chunk = i * 256 + tid;        // 0..1023
            int k  = chunk >> 5;              // 0..31
            int n4 = (chunk & 31) * 4;        // 0..124
            cp16(&Bs[buf][k][n4], W + (size_t)(k0 + k) * N + col0 + n4);
        }
        CP_COMMIT();
    };

    issue(0, 0);

    for (int kt = 0; kt < niter; kt++) {
        const int cur = kt & 1;
        if (kt + 1 < niter) {
            issue(kt + 1, cur ^ 1);
            CP_WAIT(1);                 // tile kt has landed
        } else {
            CP_WAIT(0);
        }
        __syncthreads();

#pragma unroll
        for (int ks = 0; ks < 4; ks++) {
            unsigned af[4][4], bf[4][2];
            int c = ks * 8 + r;
#pragma unroll
            for (int mt = 0; mt < 4; mt++) {
                int rr = wm * 64 + mt * 16 + q;
                af[mt][0] = f2tf32(As[cur][rr][c]);
                af[mt][1] = f2tf32(As[cur][rr + 8][c]);
                af[mt][2] = f2tf32(As[cur][rr][c + 4]);
                af[mt][3] = f2tf32(As[cur][rr + 8][c + 4]);
            }
#pragma unroll
            for (int nt = 0; nt < 4; nt++) {
                int nn = wn * 32 + nt * 8 + q;
                bf[nt][0] = f2tf32(Bs[cur][c][nn]);
                bf[nt][1] = f2tf32(Bs[cur][c + 4][nn]);
            }
#pragma unroll
            for (int mt = 0; mt < 4; mt++)
#pragma unroll
                for (int nt = 0; nt < 4; nt++)
                    mma_tf32(acc[mt][nt], af[mt], bf[nt]);
        }
        __syncthreads();   // all reads of buf cur done before it is re-filled
    }

#pragma unroll
    for (int mt = 0; mt < 4; mt++) {
        int rbase = row0 + wm * 64 + mt * 16 + q;
#pragma unroll
        for (int nt = 0; nt < 4; nt++) {
            int cbase = col0 + wn * 32 + nt * 8 + 2 * r;
            float v0 = acc[mt][nt][0];
            float v1 = acc[mt][nt][1];
            float v2 = acc[mt][nt][2];
            float v3 = acc[mt][nt][3];
            if (bias) {
                float b0 = bias[cbase], b1 = bias[cbase + 1];
                v0 += b0; v1 += b1; v2 += b0; v3 += b1;
            }
            if (relu) {
                v0 = fmaxf(v0, 0.f); v1 = fmaxf(v1, 0.f);
                v2 = fmaxf(v2, 0.f); v3 = fmaxf(v3, 0.f);
            }
            C[(size_t)rbase * N + cbase]           = v0;
            C[(size_t)rbase * N + cbase + 1]       = v1;
            C[(size_t)(rbase + 8) * N + cbase]     = v2;
            C[(size_t)(rbase + 8) * N + cbase + 1] = v3;
        }
    }
}

// ---------------- persistent LSTM scan (R7 version) -----------------------------
// 128 CTAs (32 hid-blocks x 4 batch-blocks), all co-resident (1 CTA/SM).
// Wh slice [512][64] resident in smem (tf32) for all 128 steps; c in registers.
#define SCAN_SMEM (147456 + 18432)

__global__ void bar_reset_kernel() {
    if (threadIdx.x < T_DIM) g_bar[threadIdx.x] = 0;
}

__global__ __launch_bounds__(256, 1) void lstm_scan(
    const float* __restrict__ Wh,      // [512][2048]
    const float* __restrict__ xg,      // [T][B][2048]
    const float* __restrict__ blstm,   // [2048]
    const void* __restrict__ dones,    // [T][B] bool words
    const float* __restrict__ h0,      // [B][512]
    const float* __restrict__ c0,      // [B][512]
    float* __restrict__ hbuf,          // [T][B][512]
    float* __restrict__ cst)           // [B][512]
{
    extern __shared__ char dsm[];
    unsigned (*WhS)[64][36] = (unsigned(*)[64][36])dsm;             // [16][64][36]
    unsigned (*As)[64][36]  = (unsigned(*)[64][36])(dsm + 147456);  // [2][64][36]
    float (*gsm)[68]        = (float(*)[68])(dsm + 147456);         // aliases As

    const int tid  = threadIdx.x;
    const int warp = tid >> 5;
    const int lane = tid & 31;
    const int wm = warp >> 2;        // 0..1
    const int wn = warp & 3;         // 0..3 == gate index
    const int q = lane >> 2;         // 0..7
    const int r = lane & 3;          // 0..3
    const int hid0 = blockIdx.x * 16;
    const int b0   = blockIdx.y * 64;

    // ---- load Wh slice into smem (tf32), gate-interleaved cols ----
#pragma unroll 4
    for (int kk = 0; kk < 16; kk++) {
#pragma unroll
        for (int i = 0; i < 8; i++) {
            int idx = i * 8 + warp;
            int k = (idx & 7) * 4 + r;
            int n = (idx >> 3) * 8 + q;
            int wcol = (n >> 4) * HID + hid0 + (n & 15);
            WhS[kk][n][k] = f2tf32(Wh[(size_t)(kk * 32 + k) * GDIM + wcol]);
        }
    }

    // ---- c state in registers ----
    float c_reg[4];
#pragma unroll
    for (int it = 0; it < 4; it++) {
        int idx = it * 256 + tid;
        int bl = idx >> 4, j = idx & 15;
        c_reg[it] = c0[(size_t)(b0 + bl) * HID + hid0 + j];
    }
    __syncthreads();

    const int lm0 = tid >> 3;              // A-stage row (0..31)
    const int lk4 = (tid & 7) * 4;         // A-stage k offset

    for (int t = 0; t < T_DIM; t++) {
        const float* hp = t ? (hbuf + (size_t)(t - 1) * B_DIM * HID) : h0;
        const unsigned* dn = (const unsigned*)dones + (size_t)t * B_DIM;
        const float* xgt = xg + (size_t)t * B_DIM * GDIM;

        float acc[2][2][4];
#pragma unroll
        for (int mt = 0; mt < 2; mt++)
#pragma unroll
            for (int nt = 0; nt < 2; nt++)
#pragma unroll
                for (int e = 0; e < 4; e++) acc[mt][nt][e] = 0.f;

        // prefetch A tile 0
        float4 av0, av1;
        av0 = *(const float4*)(hp + (size_t)(b0 + lm0) * HID + lk4);
        av1 = *(const float4*)(hp + (size_t)(b0 + 32 + lm0) * HID + lk4);
        if (dn[b0 + lm0] != 0u)      av0 = make_float4(0.f, 0.f, 0.f, 0.f);
        if (dn[b0 + 32 + lm0] != 0u) av1 = make_float4(0.f, 0.f, 0.f, 0.f);
        As[0][lm0][lk4 + 0] = f2tf32(av0.x);
        As[0][lm0][lk4 + 1] = f2tf32(av0.y);
        As[0][lm0][lk4 + 2] = f2tf32(av0.z);
        As[0][lm0][lk4 + 3] = f2tf32(av0.w);
        As[0][32 + lm0][lk4 + 0] = f2tf32(av1.x);
        As[0][32 + lm0][lk4 + 1] = f2tf32(av1.y);
        As[0][32 + lm0][lk4 + 2] = f2tf32(av1.z);
        As[0][32 + lm0][lk4 + 3] = f2tf32(av1.w);

#pragma unroll
        for (int kk = 0; kk < 16; kk++) {
            __syncthreads();
            if (kk < 15) {
                int k0 = (kk + 1) * 32;
                av0 = *(const float4*)(hp + (size_t)(b0 + lm0) * HID + k0 + lk4);
                av1 = *(const float4*)(hp + (size_t)(b0 + 32 + lm0) * HID + k0 + lk4);
            }
            const int cur = kk & 1;
#pragma unroll
            for (int ks = 0; ks < 4; ks++) {
                unsigned af[2][4], bf[2][2];
                int c = ks * 8 + r;
#pragma unroll
                for (int mt = 0; mt < 2; mt++) {
                    int rr = wm * 32 + mt * 16 + q;
                    af[mt][0] = As[cur][rr][c];
                    af[mt][1] = As[cur][rr + 8][c];
                    af[mt][2] = As[cur][rr][c + 4];
                    af[mt][3] = As[cur][rr + 8][c + 4];
                }
#pragma unroll
                for (int nt = 0; nt < 2; nt++) {
                    int nn = wn * 16 + nt * 8 + q;
                    bf[nt][0] = WhS[kk][nn][c];
                    bf[nt][1] = WhS[kk][nn][c + 4];
                }
#pragma unroll
                for (int mt = 0; mt < 2; mt++)
#pragma unroll
                    for (int nt = 0; nt < 2; nt++)
                        mma_tf32(acc[mt][nt], af[mt], bf[nt]);
            }
            if (kk < 15) {
                const int nxt = cur ^ 1;
                if (dn[b0 + lm0] != 0u)      av0 = make_float4(0.f, 0.f, 0.f, 0.f);
                if (dn[b0 + 32 + lm0] != 0u) av1 = make_float4(0.f, 0.f, 0.f, 0.f);
                As[nxt][lm0][lk4 + 0] = f2tf32(av0.x);
                As[nxt][lm0][lk4 + 1] = f2tf32(av0.y);
                As[nxt][lm0][lk4 + 2] = f2tf32(av0.z);
                As[nxt][lm0][lk4 + 3] = f2tf32(av0.w);
                As[nxt][32 + lm0][lk4 + 0] = f2tf32(av1.x);
                As[nxt][32 + lm0][lk4 + 1] = f2tf32(av1.y);
                As[nxt][32 + lm0][lk4 + 2] = f2tf32(av1.z);
                As[nxt][32 + lm0][lk4 + 3] = f2tf32(av1.w);
            }
        }
        __syncthreads();   // compute done before gsm (aliases As) is written

        // ---- stage gates into smem (+xg +b_lstm) ----
#pragma unroll
        for (int mt = 0; mt < 2; mt++) {
            int rl = wm * 32 + mt * 16 + q;
#pragma unroll
            for (int nt = 0; nt < 2; nt++) {
                int cl = wn * 16 + nt * 8 + 2 * r;
                int wcol = wn * HID + hid0 + nt * 8 + 2 * r;
                float2 bb = *(const float2*)(blstm + wcol);
                float2 x0 = *(const float2*)(xgt + (size_t)(b0 + rl) * GDIM + wcol);
                float2 x1 = *(const float2*)(xgt + (size_t)(b0 + rl + 8) * GDIM + wcol);
                gsm[rl][cl]         = acc[mt][nt][0] + x0.x + bb.x;
                gsm[rl][cl + 1]     = acc[mt][nt][1] + x0.y + bb.y;
                gsm[rl + 8][cl]     = acc[mt][nt][2] + x1.x + bb.x;
                gsm[rl + 8][cl + 1] = acc[mt][nt][3] + x1.y + bb.y;
            }
        }
        __syncthreads();

        // ---- pointwise LSTM update (c in registers) ----
        float* hout = hbuf + (size_t)t * B_DIM * HID;
#pragma unroll
        for (int it = 0; it < 4; it++) {
            int idx = it * 256 + tid;
            int bl = idx >> 4, j = idx & 15;
            int b = b0 + bl, hid = hid0 + j;
            float iv = gsm[bl][j];
            float fv = gsm[bl][16 + j];
            float gv = gsm[bl][32 + j];
            float ov = gsm[bl][48 + j];
            float is = 1.f / (1.f + expf(-iv));
            float fs = 1.f / (1.f + expf(-fv));
            float os = 1.f / (1.f + expf(-ov));
            float gt = tanhf(gv);
            float cm = (dn[b] != 0u) ? 0.f : c_reg[it];
            float nc = fs * cm + is * gt;
            c_reg[it] = nc;
            hout[(size_t)b * HID + hid] = os * tanhf(nc);
            if (t == T_DIM - 1)
                cst[(size_t)b * HID + hid] = nc;
        }

        // ---- grid barrier between steps ----
        if (t < T_DIM - 1) {
            __threadfence();
            __syncthreads();
            if (tid == 0) {
                atomicAdd(&g_bar[t], 1);
                while (*(volatile int*)&g_bar[t] < NCTA) { }
            }
            __syncthreads();
        }
    }
}

// ---------------- head ---------------------------------------------------------
__global__ __launch_bounds__(256) void head_kernel(
    const float* __restrict__ privo, const float* __restrict__ hbuf,
    const float* __restrict__ Wv, const float* __restrict__ bv,
    const float* __restrict__ Wa, const float* __restrict__ ba,
    float* __restrict__ outq)
{
    __shared__ float so[8][HID];
    const int tid = threadIdx.x;
    const int w = tid >> 5, lane = tid & 31;
    const int row = blockIdx.x * 8 + w;

    for (int k = lane; k < HID; k += 32)
        so[w][k] = privo[(size_t)row * HID + k] * hbuf[(size_t)row * HID + k];
    __syncwarp();

    float acc = 0.f;
    if (lane < 21) {
        for (int k = 0; k < HID; k++)
            acc += so[w][k] * Wa[k * ACT + lane];
    } else if (lane == 21) {
        for (int k = 0; k < HID; k++)
            acc += so[w][k] * Wv[k];
    }
    float v = __shfl_sync(0xffffffffu, acc, 21);
    if (lane < ACT)
        outq[(size_t)row * ACT + lane] = acc + ba[lane] + v + bv[0];
}

__global__ void tail_copy_kernel(const float* __restrict__ c,
                                 const float* __restrict__ hT,
                                 float* __restrict__ out)
{
    int i = blockIdx.x * blockDim.x + threadIdx.x;
    if (i < B_DIM * HID) {
        out[i] = c[i];
        out[B_DIM * HID + i] = hT[i];
    }
}

// -----------------------------------------------------------------------------
extern "C" void kernel_launch(void* const* d_in, const int* in_sizes, int n_in,
                              void* d_out, int out_size)
{
    const float* c0    = (const float*)d_in[0];
    const float* h0    = (const float*)d_in[1];
    const float* obs   = (const float*)d_in[2];
    const void*  dones = d_in[3];
    const float* Wp1   = (const float*)d_in[4];
    const float* bp1   = (const float*)d_in[5];
    const float* Wp2   = (const float*)d_in[6];
    const float* bp2   = (const float*)d_in[7];
    const float* Wp3   = (const float*)d_in[8];
    const float* bp3   = (const float*)d_in[9];
    const float* Wpub  = (const float*)d_in[10];
    const float* bpub  = (const float*)d_in[11];
    const float* Wi    = (const float*)d_in[12];
    const float* Wh    = (const float*)d_in[13];
    const float* blstm = (const float*)d_in[14];
    const float* Wv    = (const float*)d_in[15];
    const float* bv    = (const float*)d_in[16];
    const float* Wa    = (const float*)d_in[17];
    const float* ba    = (const float*)d_in[18];
    float* out = (float*)d_out;

    float *priv1, *tmp, *publx, *xg, *hbuf, *cst;
    cudaGetSymbolAddress((void**)&priv1, g_priv1);
    cudaGetSymbolAddress((void**)&tmp,   g_tmp);
    cudaGetSymbolAddress((void**)&publx, g_publx);
    cudaGetSymbolAddress((void**)&xg,    g_xg);
    cudaGetSymbolAddress((void**)&hbuf,  g_h);
    cudaGetSymbolAddress((void**)&cst,   g_c);

    static int smem_set = 0;
    if (!smem_set) {
        cudaFuncSetAttribute(lstm_scan,
                             cudaFuncAttributeMaxDynamicSharedMemorySize,
                             SCAN_SMEM);
        smem_set = 1;
    }

    dim3 blk(256);
    dim3 grid512(HID / BN, M_ROWS / BM);     // (4, 256)
    dim3 grid2048(GDIM / BN, M_ROWS / BM);   // (16, 256)

    // public path
    gemm_tf32<<<grid512, blk>>>(obs + PS, OBS_DIM, Wpub, HID, OBS_DIM - PS, bpub, publx, 1);
    gemm_tf32<<<grid2048, blk>>>(publx,   HID,     Wi,   GDIM, HID,        nullptr, xg, 0);
    // private path (final priv_o in priv1)
    gemm_tf32<<<grid512, blk>>>(obs,   OBS_DIM, Wp1, HID, PS,  bp1, tmp,   1);
    gemm_tf32<<<grid512, blk>>>(tmp,   HID,     Wp2, HID, HID, bp2, publx, 1);
    gemm_tf32<<<grid512, blk>>>(publx, HID,     Wp3, HID, HID, bp3, priv1, 1);

    // LSTM scan: single persistent kernel, barrier counters reset each replay
    bar_reset_kernel<<<1, 128>>>();
    lstm_scan<<<dim3(32, 4), blk, SCAN_SMEM>>>(Wh, xg, blstm, dones, h0, c0,
                                               hbuf, cst);

    // output layout
    const int STATE = B_DIM * HID;
    const int QSZ   = M_ROWS * ACT;
    float* qdst = out;
    int write_states = 0;
    if (out_size >= 2 * STATE + QSZ) { qdst = out + 2 * STATE; write_states = 1; }

    head_kernel<<<M_ROWS / 8, 256>>>(priv1, hbuf, Wv, bv, Wa, ba, qdst);

    if (write_states) {
        tail_copy_kernel<<<(STATE + 255) / 256, 256>>>(
            cst, hbuf + (size_t)(T_DIM - 1) * B_DIM * HID, out);
    }
}